// round 2
// baseline (speedup 1.0000x reference)
#include <cuda_runtime.h>
#include <cuda_bf16.h>
#include <cstdint>

// Block-sparse linear: out[M,N] = data[M,K] @ (weight[N,K] masked)^T + bias[N]
// Blocks are 32(N) x 32(K); a block is active iff any mask element in it is nonzero.
//
// Stage 1: block activity (OR-reduce each 32x32 mask tile)
// Stage 2: per n-block-row, compact list of active k-blocks
// Stage 3: GEMM with CTA tile 128(M) x 32(N); exact K-block skipping;
//          register-staged software pipeline (GMEM prefetch under FMA shadow).

#define MAX_NB 256
#define MAX_KB 256

__device__ int g_bm[MAX_NB * MAX_KB];    // block activity
__device__ int g_list[MAX_NB * MAX_KB];  // compacted active kb indices per nb
__device__ int g_cnt[MAX_NB];            // active count per nb

// ---------------------------------------------------------------------------
// Stage 1: one warp per (nb, kb) block; OR-reduce 32x32 ints.
// ---------------------------------------------------------------------------
__global__ void block_mask_kernel(const int* __restrict__ mask, int K, int Kb) {
    const int kb = blockIdx.x;
    const int nb = blockIdx.y;
    const int lane = threadIdx.x;  // 0..31, one mask row per lane
    const int4* row = reinterpret_cast<const int4*>(
        mask + (size_t)(nb * 32 + lane) * (size_t)K + (size_t)kb * 32);
    int acc = 0;
#pragma unroll
    for (int c = 0; c < 8; ++c) {
        int4 v = row[c];
        acc |= v.x | v.y | v.z | v.w;
    }
    unsigned any = __ballot_sync(0xFFFFFFFFu, acc != 0);
    if (lane == 0) g_bm[nb * Kb + kb] = (any != 0u) ? 1 : 0;
}

// ---------------------------------------------------------------------------
// Stage 2: one thread per nb scans Kb entries, writes compacted list.
// ---------------------------------------------------------------------------
__global__ void compact_kernel(int Nb, int Kb) {
    const int nb = blockIdx.x * blockDim.x + threadIdx.x;
    if (nb >= Nb) return;
    int cnt = 0;
    for (int kb = 0; kb < Kb; ++kb) {
        if (g_bm[nb * Kb + kb]) {
            g_list[nb * Kb + cnt] = kb;
            ++cnt;
        }
    }
    g_cnt[nb] = cnt;
}

// ---------------------------------------------------------------------------
// Stage 3: GEMM. CTA = 128(M) x 32(N) tile; 256 threads; 4x4 microtile.
// Both operands staged K-major in smem with XOR swizzle:
//   As element (kk, row) at word  kk*128 + 4*((row>>2) ^ (kk>>2)) + (row&3)
//   Bs element (kk, n)   at word  kk*32  + 4*((n>>2)   ^ (kk>>2)) + (n&3)
// -> conflict-free transpose stores AND conflict-free float4 compute loads.
// Pipeline: registers hold tile(it+1) while smem holds tile(it).
// ---------------------------------------------------------------------------
__global__ __launch_bounds__(256) void bs_gemm_kernel(
    const float* __restrict__ data,    // [M, K]
    const float* __restrict__ weight,  // [N, K]
    const float* __restrict__ bias,    // [N]
    float* __restrict__ out,           // [M, N]
    int M, int N, int K, int Kb)
{
    __shared__ float As[32 * 128];  // 16 KB  (kk-major, swizzled)
    __shared__ float Bs[32 * 32];   //  4 KB  (kk-major, swizzled)

    const int nb  = blockIdx.x;        // n-block row (32 output cols)
    const int m0  = blockIdx.y * 128;  // 128 output rows
    const int tid = threadIdx.x;

    const int tn  = tid & 7;   // n-group: cols 4*tn .. 4*tn+3
    const int tmg = tid >> 3;  // m-group: rows 4*tmg .. 4*tmg+3

    const int cnt = g_cnt[nb];
    const int* __restrict__ lst = g_list + nb * Kb;

    float acc[4][4];
#pragma unroll
    for (int i = 0; i < 4; ++i)
#pragma unroll
        for (int j = 0; j < 4; ++j) acc[i][j] = 0.0f;

    // data-tile load coords: 4 float4 per thread (128 rows x 8 f4 groups)
    // thread covers rows tid>>3 + 32*i, f4-col tid&7
    const int arow = tid >> 5;        // base row group 0..7 (x4 below)
    const int akq  = tid & 7;         // unused alt mapping; keep simple mapping:
    // weight-tile load coords (one float4 per thread: 32 rows x 8 f4)
    const int wrow = tid >> 3;  // n within block-row: 0..31
    const int wkq  = tid & 7;   // float4 index along k
    (void)arow; (void)akq;

    float4 ra[4];   // staged data tile
    float4 rb;      // staged weight tile

    // ---- prefetch iteration 0
    if (cnt > 0) {
        const int kb = lst[0];
        const float* dsrc = data + (size_t)m0 * (size_t)K + (size_t)kb * 32;
#pragma unroll
        for (int i = 0; i < 4; ++i) {
            const int idx = i * 256 + tid;
            const int row = idx >> 3;
            const int kq  = idx & 7;
            ra[i] = *reinterpret_cast<const float4*>(
                dsrc + (size_t)row * (size_t)K + kq * 4);
        }
        rb = *reinterpret_cast<const float4*>(
            weight + (size_t)(nb * 32 + wrow) * (size_t)K +
            (size_t)lst[0] * 32 + wkq * 4);
    }

    for (int it = 0; it < cnt; ++it) {
        // smem from previous compute is free after this barrier
        __syncthreads();

        // ---- store staged regs into swizzled smem
#pragma unroll
        for (int i = 0; i < 4; ++i) {
            const int idx = i * 256 + tid;
            const int row = idx >> 3;
            const int kq  = idx & 7;
            const int rg = row >> 2, rl = row & 3;
            const int sg = rg ^ kq;
            As[(4 * kq + 0) * 128 + 4 * sg + rl] = ra[i].x;
            As[(4 * kq + 1) * 128 + 4 * sg + rl] = ra[i].y;
            As[(4 * kq + 2) * 128 + 4 * sg + rl] = ra[i].z;
            As[(4 * kq + 3) * 128 + 4 * sg + rl] = ra[i].w;
        }
        {
            const int rg = wrow >> 2, rl = wrow & 3;
            const int sg = rg ^ wkq;
            Bs[(4 * wkq + 0) * 32 + 4 * sg + rl] = rb.x;
            Bs[(4 * wkq + 1) * 32 + 4 * sg + rl] = rb.y;
            Bs[(4 * wkq + 2) * 32 + 4 * sg + rl] = rb.z;
            Bs[(4 * wkq + 3) * 32 + 4 * sg + rl] = rb.w;
        }

        __syncthreads();

        // ---- prefetch next tile into regs (retires under FMA loop below)
        if (it + 1 < cnt) {
            const int kb = lst[it + 1];
            const float* dsrc = data + (size_t)m0 * (size_t)K + (size_t)kb * 32;
#pragma unroll
            for (int i = 0; i < 4; ++i) {
                const int idx = i * 256 + tid;
                const int row = idx >> 3;
                const int kq  = idx & 7;
                ra[i] = *reinterpret_cast<const float4*>(
                    dsrc + (size_t)row * (size_t)K + kq * 4);
            }
            rb = *reinterpret_cast<const float4*>(
                weight + (size_t)(nb * 32 + wrow) * (size_t)K +
                (size_t)kb * 32 + wkq * 4);
        }

        // ---- compute: 32 k-steps x 16 FMA
#pragma unroll
        for (int kk = 0; kk < 32; ++kk) {
            const int sw = kk >> 2;
            const float4 a = *reinterpret_cast<const float4*>(
                &As[kk * 128 + 4 * (tmg ^ sw)]);
            const float4 b = *reinterpret_cast<const float4*>(
                &Bs[kk * 32 + 4 * (tn ^ sw)]);
            const float av[4] = {a.x, a.y, a.z, a.w};
            const float bv[4] = {b.x, b.y, b.z, b.w};
#pragma unroll
            for (int i = 0; i < 4; ++i)
#pragma unroll
                for (int j = 0; j < 4; ++j)
                    acc[i][j] = fmaf(av[i], bv[j], acc[i][j]);
        }
    }

    // --- epilogue: add bias, vectorized store
    const float4 bv = *reinterpret_cast<const float4*>(bias + nb * 32 + 4 * tn);
#pragma unroll
    for (int i = 0; i < 4; ++i) {
        float4 o;
        o.x = acc[i][0] + bv.x;
        o.y = acc[i][1] + bv.y;
        o.z = acc[i][2] + bv.z;
        o.w = acc[i][3] + bv.w;
        *reinterpret_cast<float4*>(
            out + (size_t)(m0 + 4 * tmg + i) * (size_t)N + nb * 32 + 4 * tn) = o;
    }
}

// ---------------------------------------------------------------------------
// Launch
// ---------------------------------------------------------------------------
extern "C" void kernel_launch(void* const* d_in, const int* in_sizes, int n_in,
                              void* d_out, int out_size) {
    const float* data   = (const float*)d_in[0];  // [B,S,K] -> [M,K]
    const int*   mask   = (const int*)  d_in[1];  // [N,K]
    const float* weight = (const float*)d_in[2];  // [N,K]
    const float* bias   = (const float*)d_in[3];  // [N]
    float* out = (float*)d_out;                   // [M,N]

    const int N  = in_sizes[3];
    const int K  = in_sizes[2] / N;
    const int M  = in_sizes[0] / K;
    const int Nb = N / 32;
    const int Kb = K / 32;

    block_mask_kernel<<<dim3(Kb, Nb), 32>>>(mask, K, Kb);
    compact_kernel<<<(Nb + 255) / 256, 256>>>(Nb, Kb);
    bs_gemm_kernel<<<dim3(Nb, M / 128), 256>>>(data, weight, bias, out, M, N, K, Kb);
}